// round 2
// baseline (speedup 1.0000x reference)
#include <cuda_runtime.h>

// GeGate: out = y if (0 < y <= 1) else 0, where y = x * w[col] + b[col]
// x: (8192, 4096) fp32. Column-stationary threads: w/b hoisted to registers,
// each thread walks ROWS_PER_BLOCK rows of one float4-column.

#define D_DIM 4096
#define D4    (D_DIM / 4)          // 1024 float4 columns
#define ROWS_PER_BLOCK 32
#define UNROLL 4

__device__ __forceinline__ float4 gate4(float4 xv, float4 wv, float4 bv) {
    float4 y;
    y.x = fmaf(xv.x, wv.x, bv.x);
    y.y = fmaf(xv.y, wv.y, bv.y);
    y.z = fmaf(xv.z, wv.z, bv.z);
    y.w = fmaf(xv.w, wv.w, bv.w);
    y.x = (y.x > 0.0f && y.x <= 1.0f) ? y.x : 0.0f;
    y.y = (y.y > 0.0f && y.y <= 1.0f) ? y.y : 0.0f;
    y.z = (y.z > 0.0f && y.z <= 1.0f) ? y.z : 0.0f;
    y.w = (y.w > 0.0f && y.w <= 1.0f) ? y.w : 0.0f;
    return y;
}

__global__ void __launch_bounds__(256) gegate_kernel(
    const float4* __restrict__ x,
    const float4* __restrict__ w,
    const float4* __restrict__ b,
    float4* __restrict__ out)
{
    // blockIdx.x in [0,4): column group; blockIdx.y: row group.
    int c4 = blockIdx.x * blockDim.x + threadIdx.x;   // 0..1023
    float4 wv = __ldg(&w[c4]);
    float4 bv = __ldg(&b[c4]);

    size_t base = (size_t)blockIdx.y * ROWS_PER_BLOCK * D4 + c4;
    const float4* xp = x + base;
    float4* op = out + base;

    #pragma unroll
    for (int r = 0; r < ROWS_PER_BLOCK; r += UNROLL) {
        // Front-batched independent loads (MLP_p1 = 4), streaming hint.
        float4 x0 = __ldcs(xp + 0 * D4);
        float4 x1 = __ldcs(xp + 1 * D4);
        float4 x2 = __ldcs(xp + 2 * D4);
        float4 x3 = __ldcs(xp + 3 * D4);

        __stcs(op + 0 * D4, gate4(x0, wv, bv));
        __stcs(op + 1 * D4, gate4(x1, wv, bv));
        __stcs(op + 2 * D4, gate4(x2, wv, bv));
        __stcs(op + 3 * D4, gate4(x3, wv, bv));

        xp += UNROLL * D4;
        op += UNROLL * D4;
    }
}

extern "C" void kernel_launch(void* const* d_in, const int* in_sizes, int n_in,
                              void* d_out, int out_size)
{
    const float4* x = (const float4*)d_in[0];
    const float4* w = (const float4*)d_in[1];
    const float4* b = (const float4*)d_in[2];
    float4* out = (float4*)d_out;

    int rows = in_sizes[0] / D_DIM;              // 8192
    dim3 grid(D4 / 256, rows / ROWS_PER_BLOCK);  // (4, 256) = 1024 blocks
    gegate_kernel<<<grid, 256>>>(x, w, b, out);
}

// round 8
// speedup vs baseline: 1.1250x; 1.1250x over previous
#include <cuda_runtime.h>

// GeGate: out = y if (0 < y <= 1) else 0, y = x * w[col] + b[col]
// x: (8192, 4096) fp32 = 8388608 float4s.
// Grid-stride unroll-4 where the stride (total threads = 2097152 float4s) is a
// multiple of D4=1024, so all 4 elements of a thread share one column ->
// w/b loaded once per thread; 4 x-loads front-batched (MLP_p1 = 6).

#define D_DIM 4096
#define D4    (D_DIM / 4)          // 1024 float4 columns
#define D4_MASK (D4 - 1)
#define THREADS 256
#define BLOCKS  8192
#define TSTRIDE (THREADS * BLOCKS)  // 2097152, multiple of D4

__device__ __forceinline__ float4 gate4(float4 xv, float4 wv, float4 bv) {
    float4 y;
    y.x = fmaf(xv.x, wv.x, bv.x);
    y.y = fmaf(xv.y, wv.y, bv.y);
    y.z = fmaf(xv.z, wv.z, bv.z);
    y.w = fmaf(xv.w, wv.w, bv.w);
    y.x = (y.x > 0.0f && y.x <= 1.0f) ? y.x : 0.0f;
    y.y = (y.y > 0.0f && y.y <= 1.0f) ? y.y : 0.0f;
    y.z = (y.z > 0.0f && y.z <= 1.0f) ? y.z : 0.0f;
    y.w = (y.w > 0.0f && y.w <= 1.0f) ? y.w : 0.0f;
    return y;
}

__global__ void __launch_bounds__(THREADS) gegate_kernel(
    const float4* __restrict__ x,
    const float4* __restrict__ w,
    const float4* __restrict__ b,
    float4* __restrict__ out)
{
    int i = blockIdx.x * THREADS + threadIdx.x;   // 0 .. TSTRIDE-1
    int c4 = i & D4_MASK;                         // same column for all 4 elems

    // w/b: L1-resident broadcast operands
    float4 wv = __ldg(&w[c4]);
    float4 bv = __ldg(&b[c4]);

    // Front-batched independent x loads (streaming: no reuse)
    float4 x0 = __ldcs(x + i + 0 * TSTRIDE);
    float4 x1 = __ldcs(x + i + 1 * TSTRIDE);
    float4 x2 = __ldcs(x + i + 2 * TSTRIDE);
    float4 x3 = __ldcs(x + i + 3 * TSTRIDE);

    __stcs(out + i + 0 * TSTRIDE, gate4(x0, wv, bv));
    __stcs(out + i + 1 * TSTRIDE, gate4(x1, wv, bv));
    __stcs(out + i + 2 * TSTRIDE, gate4(x2, wv, bv));
    __stcs(out + i + 3 * TSTRIDE, gate4(x3, wv, bv));
}

extern "C" void kernel_launch(void* const* d_in, const int* in_sizes, int n_in,
                              void* d_out, int out_size)
{
    const float4* x = (const float4*)d_in[0];
    const float4* w = (const float4*)d_in[1];
    const float4* b = (const float4*)d_in[2];
    float4* out = (float4*)d_out;

    // out_size = 8192*4096 = 33554432 elems = 8388608 float4 = 4 * TSTRIDE
    gegate_kernel<<<BLOCKS, THREADS>>>(x, w, b, out);
}